// round 7
// baseline (speedup 1.0000x reference)
#include <cuda_runtime.h>
#include <cuda_fp16.h>
#include <cstdint>

// Problem dims (fixed): X:(B,N), boundaries:(N,K+1), weight:(N,K,E), bias:(N,E)
#define BDIM 4096
#define NDIM 64
#define KDIM 128
#define EDIM 512
#define EPS_F 1e-8f

// Prefix table T[n][k][e] (fp16): T[n][k][e] = bias[n][e] + sum_{j<k} w[n][j][e]
// out[b][n][e] = relu( lerp(T[n][bidx], T[n][bidx+1], frac) )
__device__ __half g_T16[(size_t)NDIM * (KDIM + 1) * EDIM];
// Per-(b,n) precomputed (frac, bidx), indexed b*N+n.
__device__ float2 g_SF[(size_t)BDIM * NDIM];

#define PREFIX_BLOCKS ((NDIM * 4 * (EDIM / 4)) / 256)  // 128
#define SEARCH_BLOCKS ((BDIM * NDIM) / 256)            // 1024

__device__ __forceinline__ uint2 pack4half(float4 v) {
    __half2 lo2 = __floats2half2_rn(v.x, v.y);
    __half2 hi2 = __floats2half2_rn(v.z, v.w);
    uint2 pk;
    pk.x = *(unsigned*)&lo2;
    pk.y = *(unsigned*)&hi2;
    return pk;
}

// ---------------------------------------------------------------------------
// Setup (fused):
//  blocks [0,128): prefix table, float4-vectorized redundant-chunk scan.
//    Thread = (n, k-chunk c of 32, e-group of 4). Base = redundant sum of
//    chunks < c (MLP-8 unrolled), then 32-step scan storing packed half2x2.
//  blocks [128,1152): one binary search per thread over all (b,n) -> g_SF.
// ---------------------------------------------------------------------------
__global__ void setup_kernel(const float* __restrict__ X,
                             const float* __restrict__ bnd,
                             const float* __restrict__ weight,
                             const float* __restrict__ bias) {
    if (blockIdx.x < PREFIX_BLOCKS) {
        int t = blockIdx.x * blockDim.x + threadIdx.x;   // 0 .. 32767
        int eg  = t & 127;           // e-group: e = 4*eg .. 4*eg+3
        int tmp = t >> 7;            // n*4 + c
        int c   = tmp & 3;
        int n   = tmp >> 2;

        const float4* wp = (const float4*)(weight + (size_t)n * KDIM * EDIM) + eg;
        float4 acc = ((const float4*)(bias + (size_t)n * EDIM))[eg];

        const int k0 = c * 32;
#pragma unroll 8
        for (int k = 0; k < k0; k++) {               // redundant base sum
            float4 w = wp[(size_t)k * (EDIM / 4)];
            acc.x += w.x; acc.y += w.y; acc.z += w.z; acc.w += w.w;
        }

        uint2* Trow = (uint2*)g_T16;   // 4 halves per uint2
        const size_t rowStride = EDIM / 4;           // uint2 per row
        const size_t base = (size_t)n * (KDIM + 1) * rowStride + eg;

#pragma unroll
        for (int j = 0; j < 32; j++) {
            int k = k0 + j;
            Trow[base + (size_t)k * rowStride] = pack4half(acc);
            float4 w = wp[(size_t)k * (EDIM / 4)];
            acc.x += w.x; acc.y += w.y; acc.z += w.z; acc.w += w.w;
        }
        if (c == 3)
            Trow[base + (size_t)KDIM * rowStride] = pack4half(acc);
    } else {
        int i = (blockIdx.x - PREFIX_BLOCKS) * blockDim.x + threadIdx.x; // b*N+n
        int n = i & (NDIM - 1);
        const float x = X[i];
        const float* bn = bnd + (size_t)n * (KDIM + 1);

        int lo = 0, len = KDIM - 1;
        while (len > 0) {
            int half = len >> 1;
            bool pred = __ldg(&bn[1 + lo + half]) < x;
            lo  += pred ? (half + 1) : 0;
            len  = pred ? (len - half - 1) : half;
        }
        const float s  = __ldg(&bn[lo]);
        const float eb = __ldg(&bn[lo + 1]);
        const float frac = (x - s) / (eb - s + EPS_F);
        g_SF[i] = make_float2(frac, __int_as_float(lo));
    }
}

// ---------------------------------------------------------------------------
// Gather: block = (4 consecutive b) x (8 consecutive n). Double-buffered:
// compute tile t+1 into sm[(t+1)&1] while the 16KB TMA bulk store of tile t
// is in flight (wait_group 1 backpressure before buffer reuse).
// ---------------------------------------------------------------------------
__global__ void gather_kernel(float* __restrict__ out) {
    __shared__ float4 sm[2][8][EDIM / 4];            // 2 x 16KB

    const int lane = threadIdx.x & 31;
    const int warp = threadIdx.x >> 5;
    const int n0 = blockIdx.y * 8;
    const int n  = n0 + warp;
    const int b0 = blockIdx.x * 4;

#pragma unroll
    for (int t = 0; t < 4; t++) {
        const int b = b0 + t;
        const int p = t & 1;

        if (t >= 2) {
            if (threadIdx.x == 0)
                asm volatile("cp.async.bulk.wait_group 1;" ::: "memory");
            __syncthreads();                          // buffer p is free
        }

        const float2 sf = __ldg(&g_SF[(size_t)b * NDIM + n]);
        const float frac = sf.x;
        const int   lo   = __float_as_int(sf.y);

        const uint4* T0 = (const uint4*)(g_T16 + ((size_t)n * (KDIM + 1) + lo) * EDIM);
        const uint4* T1 = T0 + (EDIM / 8);

        uint4 a0 = __ldg(&T0[lane]);
        uint4 c0 = __ldg(&T1[lane]);
        uint4 a1 = __ldg(&T0[lane + 32]);
        uint4 c1 = __ldg(&T1[lane + 32]);

#pragma unroll
        for (int j = 0; j < 2; j++) {
            const uint4& a  = j ? a1 : a0;
            const uint4& cc = j ? c1 : c0;
            const unsigned* ap = &a.x;
            const unsigned* cp = &cc.x;
            float4 r0, r1;
#pragma unroll
            for (int q = 0; q < 4; q++) {
                float2 av = __half22float2(*(const __half2*)&ap[q]);
                float2 cv = __half22float2(*(const __half2*)&cp[q]);
                float v0 = fmaxf(fmaf(frac, cv.x - av.x, av.x), 0.0f);
                float v1 = fmaxf(fmaf(frac, cv.y - av.y, av.y), 0.0f);
                if (q == 0)      { r0.x = v0; r0.y = v1; }
                else if (q == 1) { r0.z = v0; r0.w = v1; }
                else if (q == 2) { r1.x = v0; r1.y = v1; }
                else             { r1.z = v0; r1.w = v1; }
            }
            const int i = lane + 32 * j;
            sm[p][warp][2 * i]     = r0;
            sm[p][warp][2 * i + 1] = r1;
        }

        __syncthreads();                              // tile complete in SMEM

        if (threadIdx.x == 0) {
            float* gdst = out + ((size_t)b * NDIM + n0) * EDIM;
            uint32_t saddr;
            asm("{ .reg .u64 tt; cvta.to.shared.u64 tt, %1; cvt.u32.u64 %0, tt; }"
                : "=r"(saddr) : "l"(&sm[p][0][0]));
            asm volatile("fence.proxy.async.shared::cta;" ::: "memory");
            asm volatile(
                "cp.async.bulk.global.shared::cta.bulk_group [%0], [%1], %2;"
                :: "l"(gdst), "r"(saddr), "r"((int)(8 * EDIM * 4)) : "memory");
            asm volatile("cp.async.bulk.commit_group;" ::: "memory");
        }
    }

    if (threadIdx.x == 0)
        asm volatile("cp.async.bulk.wait_group 0;" ::: "memory");
}

extern "C" void kernel_launch(void* const* d_in, const int* in_sizes, int n_in,
                              void* d_out, int out_size) {
    const float* X      = (const float*)d_in[0];   // (B, N)
    const float* bnd    = (const float*)d_in[1];   // (N, K+1)
    const float* weight = (const float*)d_in[2];   // (N, K, E)
    const float* bias   = (const float*)d_in[3];   // (N, E)
    float* out = (float*)d_out;                    // (B, N, E)

    setup_kernel<<<PREFIX_BLOCKS + SEARCH_BLOCKS, 256>>>(X, bnd, weight, bias);

    dim3 grid(BDIM / 4, NDIM / 8);
    gather_kernel<<<grid, 256>>>(out);
}

// round 8
// speedup vs baseline: 1.1488x; 1.1488x over previous
#include <cuda_runtime.h>
#include <cuda_fp16.h>
#include <cstdint>

// Problem dims (fixed): X:(B,N), boundaries:(N,K+1), weight:(N,K,E), bias:(N,E)
#define BDIM 4096
#define NDIM 64
#define KDIM 128
#define EDIM 512
#define EPS_F 1e-8f
#define NCHUNK 8
#define CHK (KDIM / NCHUNK)          // 16

// Prefix table T[n][k][e] (fp16): T[n][k][e] = bias[n][e] + sum_{j<k} w[n][j][e]
// out[b][n][e] = relu( lerp(T[n][bidx], T[n][bidx+1], frac) )
__device__ __half g_T16[(size_t)NDIM * (KDIM + 1) * EDIM];
// Per-(b,n) (frac, bidx), indexed b*N+n.
__device__ float2 g_SF[(size_t)BDIM * NDIM];
// Chunk sums: S[n][c][e/2] as float2  (64*8*256 = 1MB)
__device__ float2 g_S[(size_t)NDIM * NCHUNK * (EDIM / 2)];

#define CHUNK_THREADS (NDIM * NCHUNK * (EDIM / 2))     // 131072
#define CHUNK_BLOCKS  (CHUNK_THREADS / 256)            // 512
#define SEARCH_BLOCKS ((BDIM * NDIM) / 256)            // 1024

// ---------------------------------------------------------------------------
// Setup A (fused): blocks [0,512): chunk sums S[n][c][eg] = sum of 16 k's.
//   Fully parallel, 16 float2 loads per thread, coalesced across eg.
// blocks [512,1536): binary search per (b,n) -> g_SF (independent of prefix).
// ---------------------------------------------------------------------------
__global__ void setup_a_kernel(const float* __restrict__ X,
                               const float* __restrict__ bnd,
                               const float* __restrict__ weight) {
    if (blockIdx.x < CHUNK_BLOCKS) {
        int t = blockIdx.x * blockDim.x + threadIdx.x;
        int eg  = t & 255;            // e = 2*eg
        int tmp = t >> 8;             // n*8 + c
        int c   = tmp & 7;
        int n   = tmp >> 3;

        const float2* wp = (const float2*)(weight + (size_t)n * KDIM * EDIM)
                         + (size_t)(c * CHK) * (EDIM / 2) + eg;
        float2 s = make_float2(0.f, 0.f);
#pragma unroll
        for (int j = 0; j < CHK; j++) {
            float2 w = wp[(size_t)j * (EDIM / 2)];
            s.x += w.x; s.y += w.y;
        }
        g_S[t] = s;                   // same linear index layout
    } else {
        int i = (blockIdx.x - CHUNK_BLOCKS) * blockDim.x + threadIdx.x; // b*N+n
        int n = i & (NDIM - 1);
        const float x = X[i];
        const float* bn = bnd + (size_t)n * (KDIM + 1);

        int lo = 0, len = KDIM - 1;
        while (len > 0) {
            int half = len >> 1;
            bool pred = __ldg(&bn[1 + lo + half]) < x;
            lo  += pred ? (half + 1) : 0;
            len  = pred ? (len - half - 1) : half;
        }
        const float s  = __ldg(&bn[lo]);
        const float eb = __ldg(&bn[lo + 1]);
        const float frac = (x - s) / (eb - s + EPS_F);
        g_SF[i] = make_float2(frac, __int_as_float(lo));
    }
}

// ---------------------------------------------------------------------------
// Setup B: scan. Thread = (n, c, eg): base = bias + sum of chunk sums < c
// (L2-hot), then 16-step scan (weight re-read is L2-hot from phase A),
// storing packed half2 (4B, coalesced).
// ---------------------------------------------------------------------------
__global__ void setup_b_kernel(const float* __restrict__ weight,
                               const float* __restrict__ bias) {
    int t = blockIdx.x * blockDim.x + threadIdx.x;
    int eg  = t & 255;
    int tmp = t >> 8;
    int c   = tmp & 7;
    int n   = tmp >> 3;

    float2 acc = ((const float2*)(bias + (size_t)n * EDIM))[eg];
    const float2* Sp = g_S + ((size_t)n * NCHUNK) * (EDIM / 2) + eg;
#pragma unroll
    for (int cc = 0; cc < NCHUNK - 1; cc++) {
        if (cc < c) {
            float2 s = Sp[(size_t)cc * (EDIM / 2)];
            acc.x += s.x; acc.y += s.y;
        }
    }

    const int k0 = c * CHK;
    const float2* wp = (const float2*)(weight + (size_t)n * KDIM * EDIM)
                     + (size_t)k0 * (EDIM / 2) + eg;
    unsigned* Tp = (unsigned*)g_T16 + ((size_t)n * (KDIM + 1) + k0) * (EDIM / 2) + eg;

#pragma unroll
    for (int j = 0; j < CHK; j++) {
        __half2 h = __floats2half2_rn(acc.x, acc.y);
        Tp[(size_t)j * (EDIM / 2)] = *(unsigned*)&h;
        float2 w = wp[(size_t)j * (EDIM / 2)];
        acc.x += w.x; acc.y += w.y;
    }
    if (c == NCHUNK - 1) {
        __half2 h = __floats2half2_rn(acc.x, acc.y);
        Tp[(size_t)CHK * (EDIM / 2)] = *(unsigned*)&h;
    }
}

// ---------------------------------------------------------------------------
// Gather (round-4 proven version): one warp per (b,n). Front-batched table
// LDG.128s, fp32 lerp, STS to this warp's 2KB SMEM slot, one per-warp
// cp.async.bulk TMA store. Only __syncwarp — no block barrier.
// ---------------------------------------------------------------------------
__global__ void gather_kernel(float* __restrict__ out) {
    __shared__ float4 sm[8][EDIM / 4];                 // 8 x 2KB = 16KB

    const int lane = threadIdx.x & 31;
    const int warp = threadIdx.x >> 5;
    const int n = blockIdx.y;
    const int b = blockIdx.x * 8 + warp;

    const float2 sf = __ldg(&g_SF[(size_t)b * NDIM + n]);
    const float frac = sf.x;
    const int   lo   = __float_as_int(sf.y);

    const uint4* T0 = (const uint4*)(g_T16 + ((size_t)n * (KDIM + 1) + lo) * EDIM);
    const uint4* T1 = T0 + (EDIM / 8);

    uint4 a0 = __ldg(&T0[lane]);
    uint4 c0 = __ldg(&T1[lane]);
    uint4 a1 = __ldg(&T0[lane + 32]);
    uint4 c1 = __ldg(&T1[lane + 32]);

#pragma unroll
    for (int j = 0; j < 2; j++) {
        const uint4& a  = j ? a1 : a0;
        const uint4& cc = j ? c1 : c0;
        const unsigned* ap = &a.x;
        const unsigned* cp = &cc.x;
        float4 r0, r1;
#pragma unroll
        for (int q = 0; q < 4; q++) {
            float2 av = __half22float2(*(const __half2*)&ap[q]);
            float2 cv = __half22float2(*(const __half2*)&cp[q]);
            float v0 = fmaxf(fmaf(frac, cv.x - av.x, av.x), 0.0f);
            float v1 = fmaxf(fmaf(frac, cv.y - av.y, av.y), 0.0f);
            if (q == 0)      { r0.x = v0; r0.y = v1; }
            else if (q == 1) { r0.z = v0; r0.w = v1; }
            else if (q == 2) { r1.x = v0; r1.y = v1; }
            else             { r1.z = v0; r1.w = v1; }
        }
        const int i = lane + 32 * j;
        sm[warp][2 * i]     = r0;
        sm[warp][2 * i + 1] = r1;
    }

    __syncwarp();

    if (lane == 0) {
        float* gdst = out + ((size_t)b * NDIM + n) * EDIM;
        uint32_t saddr;
        asm("{ .reg .u64 t; cvta.to.shared.u64 t, %1; cvt.u32.u64 %0, t; }"
            : "=r"(saddr) : "l"(&sm[warp][0]));
        asm volatile("fence.proxy.async.shared::cta;" ::: "memory");
        asm volatile(
            "cp.async.bulk.global.shared::cta.bulk_group [%0], [%1], %2;"
            :: "l"(gdst), "r"(saddr), "r"((int)(EDIM * 4)) : "memory");
        asm volatile("cp.async.bulk.commit_group;" ::: "memory");
        asm volatile("cp.async.bulk.wait_group 0;" ::: "memory");
    }
}

extern "C" void kernel_launch(void* const* d_in, const int* in_sizes, int n_in,
                              void* d_out, int out_size) {
    const float* X      = (const float*)d_in[0];   // (B, N)
    const float* bnd    = (const float*)d_in[1];   // (N, K+1)
    const float* weight = (const float*)d_in[2];   // (N, K, E)
    const float* bias   = (const float*)d_in[3];   // (N, E)
    float* out = (float*)d_out;                    // (B, N, E)

    setup_a_kernel<<<CHUNK_BLOCKS + SEARCH_BLOCKS, 256>>>(X, bnd, weight);
    setup_b_kernel<<<CHUNK_BLOCKS, 256>>>(weight, bias);

    dim3 grid(BDIM / 8, NDIM);
    gather_kernel<<<grid, 256>>>(out);
}